// round 4
// baseline (speedup 1.0000x reference)
#include <cuda_runtime.h>

#define NNODES 4096
#define FIN 128
#define FOUT 64
#define NHEADS 4
#define HF 256
#define NEG_INF_F (-1e9f)

// ---------------- device scratch (static allocation, allowed) ----------------
__device__ float g_mask[NNODES * NNODES];          // 64MB raw mask
__device__ float g_W[FIN * 512];                   // combined weights
__device__ float g_proj[NHEADS * NNODES * FOUT];   // [h][n][o]
__device__ float g_skip[NNODES * HF];              // [n][h*64+o]
__device__ float g_ssrc[NHEADS * NNODES];
__device__ float g_stgt[NHEADS * NNODES];
__device__ float g_rowsum[NNODES];
__device__ float g_rowsq[NNODES];
__device__ float g_colsum[NHEADS * NNODES];
__device__ float g_cinv[NHEADS * NNODES];
__device__ float g_rowmu[NNODES];
__device__ float g_rowis[NNODES];
__device__ float g_part[2 * NHEADS * NNODES * FOUT];   // 8MB partials (j-split)

// ---------------- packed f32x2 helpers ----------------
__device__ __forceinline__ unsigned long long ffma2(unsigned long long a,
                                                    unsigned long long b,
                                                    unsigned long long c) {
    unsigned long long d;
    asm("fma.rn.f32x2 %0, %1, %2, %3;" : "=l"(d) : "l"(a), "l"(b), "l"(c));
    return d;
}
__device__ __forceinline__ unsigned long long dup2(float a) {
    unsigned long long d;
    unsigned int u = __float_as_uint(a);
    asm("mov.b64 %0, {%1, %1};" : "=l"(d) : "r"(u));
    return d;
}
__device__ __forceinline__ float2 unpk(unsigned long long v) {
    unsigned int lo, hi;
    asm("mov.b64 {%0, %1}, %2;" : "=r"(lo), "=r"(hi) : "l"(v));
    return make_float2(__uint_as_float(lo), __uint_as_float(hi));
}

// ---------------- kernel Z: zero accumulators ----------------
__global__ void kZero() {
    int i = blockIdx.x * 256 + threadIdx.x;
    if (i < NHEADS * NNODES) g_colsum[i] = 0.f;
    if (i < NNODES) { g_rowsum[i] = 0.f; g_rowsq[i] = 0.f; }
}

// ---------------- kernel W0: build combined weight [128][512] ----------------
__global__ void kW0(const float* __restrict__ pp, const float* __restrict__ sw) {
    int i = blockIdx.x * 256 + threadIdx.x;   // 65536
    int k = i >> 9, c = i & 511;
    float v;
    if (c < 256) v = pp[(c >> 6) * (FIN * FOUT) + k * FOUT + (c & 63)];
    else         v = sw[(c - 256) * FIN + k];
    g_W[i] = v;
}

// ---------------- kernel P: nodes[4096x128] @ W[128x512] -> proj + skip ------
__global__ __launch_bounds__(256) void kP(const float* __restrict__ nodes) {
    __shared__ float a_s[32 * FIN];
    int t = threadIdx.x;
    int n0 = blockIdx.y * 32;
    int c = blockIdx.x * 256 + t;
#pragma unroll
    for (int r = 0; r < 16; r++) {
        int idx = r * 256 + t;
        a_s[idx] = nodes[n0 * FIN + idx];
    }
    __syncthreads();
    float acc[32];
#pragma unroll
    for (int n = 0; n < 32; n++) acc[n] = 0.f;
    for (int k4 = 0; k4 < 32; k4++) {
        float w0 = g_W[(4 * k4 + 0) * 512 + c];
        float w1 = g_W[(4 * k4 + 1) * 512 + c];
        float w2 = g_W[(4 * k4 + 2) * 512 + c];
        float w3 = g_W[(4 * k4 + 3) * 512 + c];
#pragma unroll
        for (int n = 0; n < 32; n++) {
            float4 a = *(const float4*)&a_s[n * FIN + 4 * k4];
            acc[n] = fmaf(a.x, w0, acc[n]);
            acc[n] = fmaf(a.y, w1, acc[n]);
            acc[n] = fmaf(a.z, w2, acc[n]);
            acc[n] = fmaf(a.w, w3, acc[n]);
        }
    }
    if (c < 256) {
        int h = c >> 6, o = c & 63;
        for (int n = 0; n < 32; n++)
            g_proj[(h * NNODES + n0 + n) * FOUT + o] = acc[n];
    } else {
        int cc = c - 256;
        for (int n = 0; n < 32; n++)
            g_skip[(n0 + n) * HF + cc] = acc[n];
    }
}

// ---------------- kernel S: per-node per-head scalar scores ----------------
__global__ void kS(const float* __restrict__ ssv, const float* __restrict__ stv) {
    int id = blockIdx.x * 256 + threadIdx.x;   // 16384
    int h = id >> 12, n = id & 4095;
    const float4* pr = (const float4*)&g_proj[(h * NNODES + n) * FOUT];
    const float4* a = (const float4*)(ssv + h * FOUT);
    const float4* b = (const float4*)(stv + h * FOUT);
    float s1 = 0.f, s2 = 0.f;
#pragma unroll
    for (int q = 0; q < 16; q++) {
        float4 p = pr[q];
        float4 av = __ldg(&a[q]);
        float4 bv = __ldg(&b[q]);
        s1 += p.x * av.x + p.y * av.y + p.z * av.z + p.w * av.w;
        s2 += p.x * bv.x + p.y * bv.y + p.z * bv.z + p.w * bv.w;
    }
    g_ssrc[id] = s1;
    g_stgt[id] = s2;
}

// ---------------- kernel M: mask + row stats + column exp-sums ----------------
__global__ __launch_bounds__(256) void kM(const float* __restrict__ deg,
                                          const float* __restrict__ bond,
                                          const int* __restrict__ cutp) {
    __shared__ float cs[NHEADS][128];
    int t = threadIdx.x;
    int col = t & 127, half = t >> 7;
    int j0 = blockIdx.x * 128, i0 = blockIdx.y * 128;
    float cut = (float)__ldg(cutp);
    float st[NHEADS], acc[NHEADS];
#pragma unroll
    for (int h = 0; h < NHEADS; h++) {
        st[h] = __ldg(&g_stgt[h * NNODES + j0 + col]);
        acc[h] = 0.f;
    }
    for (int s = 0; s < 64; s++) {
        int gi = i0 + 2 * s + half;
        int g = gi * NNODES + j0 + col;
        float d = deg[g], b = bond[g];
        float wdm = d + b;
        float m = (wdm > 0.f) ? wdm : ((b > cut) ? (b + wdm) : NEG_INF_F);
        g_mask[g] = m;
        float s1 = m, s2 = m * m;
#pragma unroll
        for (int off = 16; off; off >>= 1) {
            s1 += __shfl_down_sync(0xffffffffu, s1, off);
            s2 += __shfl_down_sync(0xffffffffu, s2, off);
        }
        if ((t & 31) == 0) {
            atomicAdd(&g_rowsum[gi], s1);
            atomicAdd(&g_rowsq[gi], s2);
        }
#pragma unroll
        for (int h = 0; h < NHEADS; h++) {
            float x = __ldg(&g_ssrc[h * NNODES + gi]) + st[h];
            float lr = fmaxf(x, 0.2f * x);
            acc[h] += __expf(lr + m);
        }
    }
    if (half == 1) {
#pragma unroll
        for (int h = 0; h < NHEADS; h++) cs[h][col] = acc[h];
    }
    __syncthreads();
    if (half == 0) {
#pragma unroll
        for (int h = 0; h < NHEADS; h++)
            atomicAdd(&g_colsum[h * NNODES + j0 + col], acc[h] + cs[h][col]);
    }
}

// ---------------- kernel R: finalize stats ----------------
__global__ void kR() {
    int i = blockIdx.x * 256 + threadIdx.x;
    if (i < NHEADS * NNODES) g_cinv[i] = 1.0f / g_colsum[i];
    if (i < NNODES) {
        float mu = g_rowsum[i] * (1.0f / NNODES);
        float var = fmaxf(g_rowsq[i] * (1.0f / NNODES) - mu * mu, 0.f);
        g_rowmu[i] = mu;
        g_rowis[i] = rsqrtf(var + 1e-5f);
    }
}

// ---------------- kernel A2: fused attn-gen + GEMM (256x64 tile, 8x8/thr) ----
// grid: (h=4, it=16, js=2). Each block: i in [it*256, +256), j in [js*2048, +2048)
// writes partial sums to g_part; h==0 blocks also emit mask_ln for their range.
#define JT 32
__global__ __launch_bounds__(256) void kA2(float* __restrict__ lnp) {
    __shared__ float at[JT][260];   // [j_local][i_local]
    __shared__ float pr[JT][68];    // [j_local][f]
    int t = threadIdx.x;
    int h = blockIdx.x;
    int i0 = blockIdx.y * 256;
    int js = blockIdx.z;
    // fill-phase indices
    int jl = t & 31, il = t >> 5;           // il 0..7
    // gemm-phase indices
    int tx = t & 7, ty = t >> 3;            // tx 0..7 (f), ty 0..31 (i)
    int f0 = 4 * tx;
    int iA = 4 * ty;

    unsigned long long acc[8][4];
#pragma unroll
    for (int r = 0; r < 8; r++)
#pragma unroll
        for (int c = 0; c < 4; c++) acc[r][c] = 0ull;

    const float* ssb = g_ssrc + h * NNODES;
    bool do_ln = (h == 0);

    for (int jt = 0; jt < 64; jt++) {
        int j0 = js * 2048 + jt * JT;
        int gj = j0 + jl;
        float stv = __ldg(&g_stgt[h * NNODES + gj]);
        float cvv = __ldg(&g_cinv[h * NNODES + gj]);
        // fill at (32x256) and lnp
#pragma unroll 8
        for (int r = 0; r < 32; r++) {
            int iL = il * 32 + r;
            int gi = i0 + iL;
            float m = g_mask[gi * NNODES + gj];
            float x = __ldg(&ssb[gi]) + stv;
            float lr = fmaxf(x, 0.2f * x);
            at[jl][iL] = __expf(lr + m) * cvv;
            if (do_ln)
                lnp[gi * NNODES + gj] =
                    (m - __ldg(&g_rowmu[gi])) * __ldg(&g_rowis[gi]);
        }
        // fill pr (32x64): thread -> row t>>3, 8 floats at (t&7)*8
        {
            int prow = t >> 3, pf = (t & 7) * 8;
            const float4* src =
                (const float4*)&g_proj[(h * NNODES + j0 + prow) * FOUT + pf];
            float4 v0 = src[0], v1 = src[1];
            *(float4*)&pr[prow][pf] = v0;
            *(float4*)&pr[prow][pf + 4] = v1;
        }
        __syncthreads();
#pragma unroll 4
        for (int kk = 0; kk < JT; kk++) {
            float4 aL = *(const float4*)&at[kk][iA];
            float4 aH = *(const float4*)&at[kk][iA + 128];
            ulonglong2 bL = *(const ulonglong2*)&pr[kk][f0];
            ulonglong2 bH = *(const ulonglong2*)&pr[kk][f0 + 32];
            unsigned long long d;
            d = dup2(aL.x);
            acc[0][0] = ffma2(d, bL.x, acc[0][0]); acc[0][1] = ffma2(d, bL.y, acc[0][1]);
            acc[0][2] = ffma2(d, bH.x, acc[0][2]); acc[0][3] = ffma2(d, bH.y, acc[0][3]);
            d = dup2(aL.y);
            acc[1][0] = ffma2(d, bL.x, acc[1][0]); acc[1][1] = ffma2(d, bL.y, acc[1][1]);
            acc[1][2] = ffma2(d, bH.x, acc[1][2]); acc[1][3] = ffma2(d, bH.y, acc[1][3]);
            d = dup2(aL.z);
            acc[2][0] = ffma2(d, bL.x, acc[2][0]); acc[2][1] = ffma2(d, bL.y, acc[2][1]);
            acc[2][2] = ffma2(d, bH.x, acc[2][2]); acc[2][3] = ffma2(d, bH.y, acc[2][3]);
            d = dup2(aL.w);
            acc[3][0] = ffma2(d, bL.x, acc[3][0]); acc[3][1] = ffma2(d, bL.y, acc[3][1]);
            acc[3][2] = ffma2(d, bH.x, acc[3][2]); acc[3][3] = ffma2(d, bH.y, acc[3][3]);
            d = dup2(aH.x);
            acc[4][0] = ffma2(d, bL.x, acc[4][0]); acc[4][1] = ffma2(d, bL.y, acc[4][1]);
            acc[4][2] = ffma2(d, bH.x, acc[4][2]); acc[4][3] = ffma2(d, bH.y, acc[4][3]);
            d = dup2(aH.y);
            acc[5][0] = ffma2(d, bL.x, acc[5][0]); acc[5][1] = ffma2(d, bL.y, acc[5][1]);
            acc[5][2] = ffma2(d, bH.x, acc[5][2]); acc[5][3] = ffma2(d, bH.y, acc[5][3]);
            d = dup2(aH.z);
            acc[6][0] = ffma2(d, bL.x, acc[6][0]); acc[6][1] = ffma2(d, bL.y, acc[6][1]);
            acc[6][2] = ffma2(d, bH.x, acc[6][2]); acc[6][3] = ffma2(d, bH.y, acc[6][3]);
            d = dup2(aH.w);
            acc[7][0] = ffma2(d, bL.x, acc[7][0]); acc[7][1] = ffma2(d, bL.y, acc[7][1]);
            acc[7][2] = ffma2(d, bH.x, acc[7][2]); acc[7][3] = ffma2(d, bH.y, acc[7][3]);
        }
        __syncthreads();
    }
    // store partials: rows iA+rr (rg=0) and iA+128+rr (rg=1), f0 and f0+32
    float* pbase = g_part + ((size_t)(js * NHEADS + h)) * (NNODES * FOUT);
#pragma unroll
    for (int rg = 0; rg < 2; rg++) {
#pragma unroll
        for (int rr = 0; rr < 4; rr++) {
            int gi = i0 + iA + rr + rg * 128;
            float2 lo0 = unpk(acc[rg * 4 + rr][0]);
            float2 hi0 = unpk(acc[rg * 4 + rr][1]);
            float2 lo1 = unpk(acc[rg * 4 + rr][2]);
            float2 hi1 = unpk(acc[rg * 4 + rr][3]);
            *(float4*)&pbase[gi * FOUT + f0] =
                make_float4(lo0.x, lo0.y, hi0.x, hi0.y);
            *(float4*)&pbase[gi * FOUT + f0 + 32] =
                make_float4(lo1.x, lo1.y, hi1.x, hi1.y);
        }
    }
}

// ---------------- kernel C: combine partials + skip + ELU ----------------
// out has 4096*256 floats = 262144 float4s -> 1024 blocks * 256 threads.
__global__ void kC(float* __restrict__ outp) {
    int id = blockIdx.x * 256 + threadIdx.x;   // 0 .. 262143
    int nf = id * 4;                            // index into [n][256]
    int n = nf >> 8;
    int c = nf & 255;
    int h = c >> 6, f = c & 63;
    float4 p0 = *(const float4*)&g_part[((size_t)(0 * NHEADS + h) * NNODES + n) * FOUT + f];
    float4 p1 = *(const float4*)&g_part[((size_t)(1 * NHEADS + h) * NNODES + n) * FOUT + f];
    float4 sk = *(const float4*)&g_skip[n * HF + c];
    float v0 = p0.x + p1.x + sk.x;
    float v1 = p0.y + p1.y + sk.y;
    float v2 = p0.z + p1.z + sk.z;
    float v3 = p0.w + p1.w + sk.w;
    v0 = v0 > 0.f ? v0 : expm1f(v0);
    v1 = v1 > 0.f ? v1 : expm1f(v1);
    v2 = v2 > 0.f ? v2 : expm1f(v2);
    v3 = v3 > 0.f ? v3 : expm1f(v3);
    *(float4*)&outp[nf] = make_float4(v0, v1, v2, v3);
}

// ---------------- host launch ----------------
extern "C" void kernel_launch(void* const* d_in, const int* in_sizes, int n_in,
                              void* d_out, int out_size) {
    const float* nodes = (const float*)d_in[0];
    const float* deg   = (const float*)d_in[1];
    const float* bond  = (const float*)d_in[3];
    const float* pp    = (const float*)d_in[4];
    const float* ssv   = (const float*)d_in[5];
    const float* stv   = (const float*)d_in[6];
    const float* sw    = (const float*)d_in[7];
    const int*   cutp  = (const int*)d_in[8];

    float* outp = (float*)d_out;                       // [4096, 256]
    float* lnp  = outp + NNODES * HF;                  // [4096, 4096]

    kZero<<<64, 256>>>();
    kW0<<<256, 256>>>(pp, sw);
    kP<<<dim3(2, 128), 256>>>(nodes);
    kS<<<64, 256>>>(ssv, stv);
    kM<<<dim3(32, 32), 256>>>(deg, bond, cutp);
    kR<<<64, 256>>>();
    kA2<<<dim3(4, 16, 2), 256>>>(lnp);
    kC<<<1024, 256>>>(outp);
}

// round 5
// speedup vs baseline: 1.6477x; 1.6477x over previous
#include <cuda_runtime.h>
#include <math.h>

#define NN 4096
#define FIN 128
#define FOUT 64
#define NHEADS 4
#define HF 256
#define NEG_INF_F (-1e9f)

// ---------------- device scratch ----------------
__device__ float g_mask[NN * NN];                  // 64MB raw mask
__device__ float g_proj[NHEADS * NN * FOUT];       // [h][n][o]
__device__ float g_skip[NN * HF];                  // [n][h*64+o]
__device__ float g_ssrc[NHEADS * NN];
__device__ float g_stgt[NHEADS * NN];
__device__ float g_rowsum[NN];
__device__ float g_rowsq[NN];
__device__ float g_colsum[NHEADS * NN];
__device__ float g_part[4 * NHEADS * NN * FOUT];   // 16.8MB partials (4 j-splits)

// ---------------- packed f32x2 helpers ----------------
__device__ __forceinline__ unsigned long long ffma2(unsigned long long a,
                                                    unsigned long long b,
                                                    unsigned long long c) {
    unsigned long long d;
    asm("fma.rn.f32x2 %0, %1, %2, %3;" : "=l"(d) : "l"(a), "l"(b), "l"(c));
    return d;
}
__device__ __forceinline__ unsigned long long dup2(float a) {
    unsigned long long d;
    unsigned int u = __float_as_uint(a);
    asm("mov.b64 %0, {%1, %1};" : "=l"(d) : "r"(u));
    return d;
}
__device__ __forceinline__ float2 unpk(unsigned long long v) {
    unsigned int lo, hi;
    asm("mov.b64 {%0, %1}, %2;" : "=r"(lo), "=r"(hi) : "l"(v));
    return make_float2(__uint_as_float(lo), __uint_as_float(hi));
}

// ---- launch 0: kP2 — nodes[4096x128] @ [proj|skip] -> g_proj, g_skip -------
// grid (2, 64), block 256. x=0: proj columns (c=t, 0..255); x=1: skip columns.
__global__ __launch_bounds__(256) void kP2(const float* __restrict__ nodes,
                                           const float* __restrict__ pp,
                                           const float* __restrict__ sw) {
    __shared__ float a_s[64 * FIN];   // 32KB
    int t = threadIdx.x;
    int n0 = blockIdx.y * 64;
    int isw = blockIdx.x;             // 0 = proj, 1 = skip
#pragma unroll
    for (int r = 0; r < 32; r++)
        a_s[r * 256 + t] = nodes[n0 * FIN + r * 256 + t];
    __syncthreads();

    float acc[64];
#pragma unroll
    for (int n = 0; n < 64; n++) acc[n] = 0.f;

    if (isw == 0) {
        int h = t >> 6, o = t & 63;
        const float* wcol = pp + h * (FIN * FOUT) + o;   // stride 64 over k
        for (int k4 = 0; k4 < 32; k4++) {
            float w0 = __ldg(&wcol[(4 * k4 + 0) * FOUT]);
            float w1 = __ldg(&wcol[(4 * k4 + 1) * FOUT]);
            float w2 = __ldg(&wcol[(4 * k4 + 2) * FOUT]);
            float w3 = __ldg(&wcol[(4 * k4 + 3) * FOUT]);
#pragma unroll
            for (int n = 0; n < 64; n++) {
                float4 a = *(const float4*)&a_s[n * FIN + 4 * k4];
                acc[n] = fmaf(a.x, w0, acc[n]);
                acc[n] = fmaf(a.y, w1, acc[n]);
                acc[n] = fmaf(a.z, w2, acc[n]);
                acc[n] = fmaf(a.w, w3, acc[n]);
            }
        }
        for (int n = 0; n < 64; n++)
            g_proj[(h * NN + n0 + n) * FOUT + o] = acc[n];
    } else {
        const float* wcol = sw + t * FIN;   // contiguous over k (L1-friendly)
        for (int k4 = 0; k4 < 32; k4++) {
            float4 w = __ldg((const float4*)&wcol[4 * k4]);
#pragma unroll
            for (int n = 0; n < 64; n++) {
                float4 a = *(const float4*)&a_s[n * FIN + 4 * k4];
                acc[n] = fmaf(a.x, w.x, acc[n]);
                acc[n] = fmaf(a.y, w.y, acc[n]);
                acc[n] = fmaf(a.z, w.z, acc[n]);
                acc[n] = fmaf(a.w, w.w, acc[n]);
            }
        }
        for (int n = 0; n < 64; n++)
            g_skip[(n0 + n) * HF + t] = acc[n];
    }
}

// ---- launch 1: kSZ — per-node per-head scalar scores + zero accumulators ---
__global__ void kSZ(const float* __restrict__ ssv, const float* __restrict__ stv) {
    int id = blockIdx.x * 256 + threadIdx.x;   // 16384
    g_colsum[id] = 0.f;
    if (id < NN) { g_rowsum[id] = 0.f; g_rowsq[id] = 0.f; }
    int h = id >> 12, n = id & 4095;
    const float4* pr = (const float4*)&g_proj[(h * NN + n) * FOUT];
    const float4* a = (const float4*)(ssv + h * FOUT);
    const float4* b = (const float4*)(stv + h * FOUT);
    float s1 = 0.f, s2 = 0.f;
#pragma unroll
    for (int q = 0; q < 16; q++) {
        float4 p = pr[q];
        float4 av = __ldg(&a[q]);
        float4 bv = __ldg(&b[q]);
        s1 += p.x * av.x + p.y * av.y + p.z * av.z + p.w * av.w;
        s2 += p.x * bv.x + p.y * bv.y + p.z * bv.z + p.w * bv.w;
    }
    g_ssrc[id] = s1;
    g_stgt[id] = s2;
}

// ---- launch 2: kM — mask + row stats + column exp-sums ----
__global__ __launch_bounds__(256) void kM(const float* __restrict__ deg,
                                          const float* __restrict__ bond,
                                          const int* __restrict__ cutp) {
    __shared__ float cs[NHEADS][128];
    int t = threadIdx.x;
    int col = t & 127, half = t >> 7;
    int j0 = blockIdx.x * 128, i0 = blockIdx.y * 128;
    float cut = (float)__ldg(cutp);
    float st[NHEADS], acc[NHEADS];
#pragma unroll
    for (int h = 0; h < NHEADS; h++) {
        st[h] = __ldg(&g_stgt[h * NN + j0 + col]);
        acc[h] = 0.f;
    }
    for (int s = 0; s < 64; s++) {
        int gi = i0 + 2 * s + half;
        int g = gi * NN + j0 + col;
        float d = deg[g], b = bond[g];
        float wdm = d + b;
        float m = (wdm > 0.f) ? wdm : ((b > cut) ? (b + wdm) : NEG_INF_F);
        g_mask[g] = m;
        float s1 = m, s2 = m * m;
#pragma unroll
        for (int off = 16; off; off >>= 1) {
            s1 += __shfl_down_sync(0xffffffffu, s1, off);
            s2 += __shfl_down_sync(0xffffffffu, s2, off);
        }
        if ((t & 31) == 0) {
            atomicAdd(&g_rowsum[gi], s1);
            atomicAdd(&g_rowsq[gi], s2);
        }
#pragma unroll
        for (int h = 0; h < NHEADS; h++) {
            float x = __ldg(&g_ssrc[h * NN + gi]) + st[h];
            float lr = fmaxf(x, 0.2f * x);
            acc[h] += __expf(lr + m);
        }
    }
    if (half == 1) {
#pragma unroll
        for (int h = 0; h < NHEADS; h++) cs[h][col] = acc[h];
    }
    __syncthreads();
    if (half == 0) {
#pragma unroll
        for (int h = 0; h < NHEADS; h++)
            atomicAdd(&g_colsum[h * NN + j0 + col], acc[h] + cs[h][col]);
    }
}

// ---- launch 3: kA3 — fused stats-finalize + attn-gen + GEMM + mask_ln ------
// grid (4h, 16it, 4js) = 256 CTAs (2/SM). Tile: 256 i x 64 f x 1024 j.
// at stored [i][j] pitch 33 (conflict-free STS); 1/colsum folded into pr tile.
#define ATP 33
#define PRP 68
__global__ __launch_bounds__(256, 2) void kA3(float* __restrict__ lnp) {
    __shared__ float at[256 * ATP];   // 33.8KB
    __shared__ float pr[32 * PRP];    // 8.7KB
    __shared__ float smu[256], sis[256];
    int t = threadIdx.x;
    int h = blockIdx.x;
    int i0 = blockIdx.y * 256;
    int jbase = blockIdx.z * 1024;
    bool do_ln = (h == 0);

    // inline row stats (replaces kR) — only needed for mask_ln
    if (do_ln) {
        float rs = g_rowsum[i0 + t];
        float rq = g_rowsq[i0 + t];
        float mu = rs * (1.0f / NN);
        float var = fmaxf(rq * (1.0f / NN) - mu * mu, 0.f);
        smu[t] = mu;
        sis[t] = rsqrtf(var + 1e-5f);
    }
    __syncthreads();

    // fill-phase indices
    int jf = t & 31, ig = t >> 5;          // at fill: 32 j lanes x 8 i-groups
    int prow = t >> 3, pf = (t & 7) * 8;   // pr fill
    // gemm-phase indices
    int tx = t & 7, ty = t >> 3;
    int f0 = 4 * tx, iA = 4 * ty;

    unsigned long long acc[8][4];
#pragma unroll
    for (int r = 0; r < 8; r++)
#pragma unroll
        for (int c = 0; c < 4; c++) acc[r][c] = 0ull;

    const float* ssb = g_ssrc + h * NN;
    const float* stb = g_stgt + h * NN;

    for (int jt = 0; jt < 32; jt++) {
        int j0 = jbase + jt * 32;
        // pr fill: pr[j][f] = proj[j][f] * (1/colsum[j])
        {
            float cvv = __fdividef(1.0f, __ldg(&g_colsum[h * NN + j0 + prow]));
            const float4* src =
                (const float4*)&g_proj[(h * NN + j0 + prow) * FOUT + pf];
            float4 v0 = src[0], v1 = src[1];
            v0.x *= cvv; v0.y *= cvv; v0.z *= cvv; v0.w *= cvv;
            v1.x *= cvv; v1.y *= cvv; v1.z *= cvv; v1.w *= cvv;
            *(float4*)&pr[prow * PRP + pf] = v0;
            *(float4*)&pr[prow * PRP + pf + 4] = v1;
        }
        // at fill: at[i][j] = exp(leaky(ssrc[i]+stgt[j]) + mask[i][j]); + lnp
        float stv = __ldg(&stb[j0 + jf]);
#pragma unroll 4
        for (int r = 0; r < 32; r++) {
            int i = ig * 32 + r;
            int gi = i0 + i;
            float m = g_mask[gi * NN + j0 + jf];
            float x = __ldg(&ssb[gi]) + stv;
            float lr = fmaxf(x, 0.2f * x);
            at[i * ATP + jf] = __expf(lr + m);
            if (do_ln)
                lnp[gi * NN + j0 + jf] = (m - smu[i]) * sis[i];
        }
        __syncthreads();
        // GEMM: 8i x 8f per thread, scalar a loads (broadcast), packed b
#pragma unroll 4
        for (int kk = 0; kk < 32; kk++) {
            const float* ab = at + kk;
            ulonglong2 bL = *(const ulonglong2*)&pr[kk * PRP + f0];
            ulonglong2 bH = *(const ulonglong2*)&pr[kk * PRP + f0 + 32];
            unsigned long long d;
            float a0 = ab[(iA + 0) * ATP];
            float a1 = ab[(iA + 1) * ATP];
            float a2 = ab[(iA + 2) * ATP];
            float a3 = ab[(iA + 3) * ATP];
            float a4 = ab[(iA + 128) * ATP];
            float a5 = ab[(iA + 129) * ATP];
            float a6 = ab[(iA + 130) * ATP];
            float a7 = ab[(iA + 131) * ATP];
            d = dup2(a0);
            acc[0][0] = ffma2(d, bL.x, acc[0][0]); acc[0][1] = ffma2(d, bL.y, acc[0][1]);
            acc[0][2] = ffma2(d, bH.x, acc[0][2]); acc[0][3] = ffma2(d, bH.y, acc[0][3]);
            d = dup2(a1);
            acc[1][0] = ffma2(d, bL.x, acc[1][0]); acc[1][1] = ffma2(d, bL.y, acc[1][1]);
            acc[1][2] = ffma2(d, bH.x, acc[1][2]); acc[1][3] = ffma2(d, bH.y, acc[1][3]);
            d = dup2(a2);
            acc[2][0] = ffma2(d, bL.x, acc[2][0]); acc[2][1] = ffma2(d, bL.y, acc[2][1]);
            acc[2][2] = ffma2(d, bH.x, acc[2][2]); acc[2][3] = ffma2(d, bH.y, acc[2][3]);
            d = dup2(a3);
            acc[3][0] = ffma2(d, bL.x, acc[3][0]); acc[3][1] = ffma2(d, bL.y, acc[3][1]);
            acc[3][2] = ffma2(d, bH.x, acc[3][2]); acc[3][3] = ffma2(d, bH.y, acc[3][3]);
            d = dup2(a4);
            acc[4][0] = ffma2(d, bL.x, acc[4][0]); acc[4][1] = ffma2(d, bL.y, acc[4][1]);
            acc[4][2] = ffma2(d, bH.x, acc[4][2]); acc[4][3] = ffma2(d, bH.y, acc[4][3]);
            d = dup2(a5);
            acc[5][0] = ffma2(d, bL.x, acc[5][0]); acc[5][1] = ffma2(d, bL.y, acc[5][1]);
            acc[5][2] = ffma2(d, bH.x, acc[5][2]); acc[5][3] = ffma2(d, bH.y, acc[5][3]);
            d = dup2(a6);
            acc[6][0] = ffma2(d, bL.x, acc[6][0]); acc[6][1] = ffma2(d, bL.y, acc[6][1]);
            acc[6][2] = ffma2(d, bH.x, acc[6][2]); acc[6][3] = ffma2(d, bH.y, acc[6][3]);
            d = dup2(a7);
            acc[7][0] = ffma2(d, bL.x, acc[7][0]); acc[7][1] = ffma2(d, bL.y, acc[7][1]);
            acc[7][2] = ffma2(d, bH.x, acc[7][2]); acc[7][3] = ffma2(d, bH.y, acc[7][3]);
        }
        __syncthreads();
    }
    // store partials
    float* pbase = g_part + ((size_t)(blockIdx.z * NHEADS + h)) * (NN * FOUT);
#pragma unroll
    for (int r = 0; r < 8; r++) {
        int gi = i0 + (r < 4 ? iA + r : iA + 124 + r);   // iA+128+(r-4)
        float2 lo0 = unpk(acc[r][0]);
        float2 hi0 = unpk(acc[r][1]);
        float2 lo1 = unpk(acc[r][2]);
        float2 hi1 = unpk(acc[r][3]);
        *(float4*)&pbase[gi * FOUT + f0] = make_float4(lo0.x, lo0.y, hi0.x, hi0.y);
        *(float4*)&pbase[gi * FOUT + f0 + 32] = make_float4(lo1.x, lo1.y, hi1.x, hi1.y);
    }
}

// ---- launch 4: kC — combine 4 partials + skip + ELU ----
__global__ void kC(float* __restrict__ outp) {
    int id = blockIdx.x * 256 + threadIdx.x;   // 0 .. 262143
    int nf = id * 4;
    int n = nf >> 8;
    int c = nf & 255;
    int h = c >> 6, f = c & 63;
    size_t base = ((size_t)h * NN + n) * FOUT + f;
    const size_t stride = (size_t)NHEADS * NN * FOUT;
    float4 p0 = *(const float4*)&g_part[base];
    float4 p1 = *(const float4*)&g_part[base + stride];
    float4 p2 = *(const float4*)&g_part[base + 2 * stride];
    float4 p3 = *(const float4*)&g_part[base + 3 * stride];
    float4 sk = *(const float4*)&g_skip[n * HF + c];
    float v0 = (p0.x + p1.x) + (p2.x + p3.x) + sk.x;
    float v1 = (p0.y + p1.y) + (p2.y + p3.y) + sk.y;
    float v2 = (p0.z + p1.z) + (p2.z + p3.z) + sk.z;
    float v3 = (p0.w + p1.w) + (p2.w + p3.w) + sk.w;
    v0 = v0 > 0.f ? v0 : expm1f(v0);
    v1 = v1 > 0.f ? v1 : expm1f(v1);
    v2 = v2 > 0.f ? v2 : expm1f(v2);
    v3 = v3 > 0.f ? v3 : expm1f(v3);
    *(float4*)&outp[nf] = make_float4(v0, v1, v2, v3);
}

// ---------------- host launch ----------------
extern "C" void kernel_launch(void* const* d_in, const int* in_sizes, int n_in,
                              void* d_out, int out_size) {
    const float* nodes = (const float*)d_in[0];
    const float* deg   = (const float*)d_in[1];
    const float* bond  = (const float*)d_in[3];
    const float* pp    = (const float*)d_in[4];
    const float* ssv   = (const float*)d_in[5];
    const float* stv   = (const float*)d_in[6];
    const float* sw    = (const float*)d_in[7];
    const int*   cutp  = (const int*)d_in[8];

    float* outp = (float*)d_out;            // [4096, 256]
    float* lnp  = outp + NN * HF;           // [4096, 4096]

    kP2<<<dim3(2, 64), 256>>>(nodes, pp, sw);
    kSZ<<<64, 256>>>(ssv, stv);
    kM<<<dim3(32, 32), 256>>>(deg, bond, cutp);
    kA3<<<dim3(4, 16, 4), 256>>>(lnp);
    kC<<<1024, 256>>>(outp);
}